// round 7
// baseline (speedup 1.0000x reference)
#include <cuda_runtime.h>

// Problem constants (fixed shapes: T=1, C=8, E=4, H=W=64)
#define HP   66            // padded H=W (64+2)
#define QQ   4356          // HP*HP
#define HO   64            // original H=W
#define WSZ  15            // search window side
#define NC   225           // WSZ*WSZ candidates
#define KS   64            // top-k kept
#define KAGG 7             // aggregated volumes
#define BIGD 1e10f

// ---------------- scratch (device globals; no allocation allowed) ------------
__device__ float4 g_pexT4[16 * QQ];       // xe patch embeddings, TRANSPOSED [chunk][q]
__device__ float4 g_pey4 [QQ * 16];       // (Q,64) ye patch embeddings (row-major)
__device__ float4 g_px4  [QQ * 32];       // (Q,128) x patches
__device__ float4 g_zp4  [QQ * KAGG * 32];// (Q,7,128) weighted patch sums
__device__ float  g_w    [QQ * 512];      // (Q,64,8) weights, [o*8+k], k<7 used
__device__ int    g_inds [QQ * KS];       // selected candidate pixel indices
__device__ float  g_qn   [QQ];            // ||pey||^2
__device__ float  g_tau  [QQ];            // exp(avg log_temp patch)

// ---------------- kernel 0: x patches ---------------------------------------
__global__ void px_kernel(const float* __restrict__ x) {
    int q = blockIdx.x, tid = threadIdx.x;          // 128 threads
    int qi = q / HP, qj = q % HP;
    int p = tid & 15, ch = tid >> 4;
    int a = p >> 2, b = p & 3;
    int i = qi + a - 3, j = qj + b - 3;
    bool inb = ((unsigned)i < 64u) && ((unsigned)j < 64u);
    ((float*)g_px4)[q * 128 + tid] = inb ? x[ch * 4096 + i * 64 + j] : 0.f;
}

// ---------------- kernel 1: xe/ye patches + norm + temperature ---------------
__global__ void embed_kernel(const float* __restrict__ xe,
                             const float* __restrict__ ye,
                             const float* __restrict__ ltin) {
    int q = blockIdx.x, tid = threadIdx.x;          // 64 threads
    int qi = q / HP, qj = q % HP;
    int p = tid & 15, ch = tid >> 4;                // ch 0..3, d = ch*16+p = tid
    int a = p >> 2, b = p & 3;
    int i = qi + a - 3, j = qj + b - 3;             // original-image coords
    bool inb = ((unsigned)i < 64u) && ((unsigned)j < 64u);

    float vx = inb ? xe[ch * 4096 + i * 64 + j] : 0.f;
    float vy = inb ? ye[ch * 4096 + i * 64 + j] : 0.f;
    // transposed xe storage: float index chunk*(QQ*4) + q*4 + comp
    ((float*)g_pexT4)[(tid >> 2) * (QQ * 4) + q * 4 + (tid & 3)] = vx;
    ((float*)g_pey4)[q * 64 + tid] = vy;

    __shared__ float sm[64];
    sm[tid] = vy * vy;
    __syncthreads();
    for (int st = 32; st > 0; st >>= 1) { if (tid < st) sm[tid] += sm[tid + st]; __syncthreads(); }
    if (tid == 0) g_qn[q] = sm[0];
    __syncthreads();

    float lv = 0.f;
    if (tid < 16 && inb) lv = ltin[i * 64 + j];      // tid<16 -> ch==0, p==tid
    sm[tid] = (tid < 16) ? lv : 0.f;
    __syncthreads();
    for (int st = 32; st > 0; st >>= 1) { if (tid < st) sm[tid] += sm[tid + st]; __syncthreads(); }
    if (tid == 0) g_tau[q] = expf(sm[0] * (1.f / 16.f));
}

// ---------------- kernel 2: passthrough of y into first 8 output channels ---
__global__ void copy_y_kernel(const float* __restrict__ y, float* __restrict__ out) {
    int idx = blockIdx.x * blockDim.x + threadIdx.x; // 32768 threads
    out[idx] = y[idx];
}

// ---------------- kernel 3: tiled distances + top-64 + NNN weights ----------
// One block = 2x2 query tile. Shared 16x16 candidate-window union staged in
// smem (two passes of 8 float4-chunks), candidate norms computed during load.
__global__ void dist_kernel() {
    int tid = threadIdx.x;                           // 256 threads
    int bi = blockIdx.x;                             // 33*33 tiles
    int tile_i = (bi / 33) * 2, tile_j = (bi % 33) * 2;

    __shared__ float4 wsm[8][256];                   // 32KB window chunk-slab
    __shared__ float  dv [4][256];                   // cross / final dists
    __shared__ unsigned long long keys[4][256];      // 8KB sort keys
    __shared__ float  cns[256];                      // candidate norms
    __shared__ float4 peys[4][16];                   // query embeddings

    int topr0  = min(max(tile_i - 7, 0), HP - WSZ);
    int leftc0 = min(max(tile_j - 7, 0), HP - WSZ);

    // per-query window anchors (offset 0/1 from union base)
    int toprl[4], leftcl[4], qpix[4];
    #pragma unroll
    for (int ql = 0; ql < 4; ql++) {
        int qi = tile_i + (ql >> 1), qj = tile_j + (ql & 1);
        toprl[ql]  = min(max(qi - 7, 0), HP - WSZ);
        leftcl[ql] = min(max(qj - 7, 0), HP - WSZ);
        qpix[ql]   = qi * HP + qj;
    }

    if (tid < 64) peys[tid >> 4][tid & 15] = g_pey4[qpix[tid >> 4] * 16 + (tid & 15)];

    // candidate pixel for this thread (clamped; clamped slots never referenced)
    int crow = min(topr0 + (tid >> 4), HP - 1);
    int ccol = min(leftc0 + (tid & 15), HP - 1);
    int cpix = crow * HP + ccol;

    float cnacc = 0.f;
    float crossA[4];

    // ---- pass 0: chunks 0..7 ----
    #pragma unroll
    for (int i = 0; i < 8; i++) {
        float4 v = g_pexT4[i * QQ + cpix];
        wsm[i][tid] = v;
        cnacc += v.x * v.x + v.y * v.y + v.z * v.z + v.w * v.w;
    }
    __syncthreads();
    {
        int wr = tid / WSZ, wc = tid - wr * WSZ;     // window-local coords
        #pragma unroll
        for (int ql = 0; ql < 4; ql++) {
            float acc = 0.f;
            if (tid < NC) {
                int cidx = (wr + toprl[ql] - topr0) * 16 + (wc + leftcl[ql] - leftc0);
                #pragma unroll
                for (int i = 0; i < 8; i++) {
                    float4 v = wsm[i][cidx]; float4 u = peys[ql][i];
                    acc += v.x * u.x + v.y * u.y + v.z * u.z + v.w * u.w;
                }
            }
            crossA[ql] = acc;
        }
    }
    __syncthreads();

    // ---- pass 1: chunks 8..15 ----
    #pragma unroll
    for (int i = 0; i < 8; i++) {
        float4 v = g_pexT4[(8 + i) * QQ + cpix];
        wsm[i][tid] = v;
        cnacc += v.x * v.x + v.y * v.y + v.z * v.z + v.w * v.w;
    }
    cns[tid] = cnacc;
    __syncthreads();
    {
        int wr = tid / WSZ, wc = tid - wr * WSZ;
        #pragma unroll
        for (int ql = 0; ql < 4; ql++) {
            float d = 1e30f;
            if (tid < NC) {
                int cidx = (wr + toprl[ql] - topr0) * 16 + (wc + leftcl[ql] - leftc0);
                float acc = crossA[ql];
                #pragma unroll
                for (int i = 0; i < 8; i++) {
                    float4 v = wsm[i][cidx]; float4 u = peys[ql][8 + i];
                    acc += v.x * u.x + v.y * u.y + v.z * u.z + v.w * u.w;
                }
                int pr = toprl[ql] + wr, pc = leftcl[ql] + wc;
                int pix = pr * HP + pc;
                d = g_qn[qpix[ql]] + cns[cidx] - 2.f * acc;
                if (pix == qpix[ql]) d = BIGD;       // remove_self
            }
            dv[ql][tid] = d;
            unsigned u = __float_as_uint(d);
            u = (u & 0x80000000u) ? ~u : (u | 0x80000000u);
            unsigned long long key = ((unsigned long long)u << 32) | (unsigned)tid;
            if (tid >= NC) key = 0xFFFFFFFFFFFFFFFFull;
            keys[ql][tid] = key;
        }
    }
    __syncthreads();

    // ---- bitonic sort: 4 independent 256-segments, barriers amortized ----
    for (int k = 2; k <= 256; k <<= 1)
        for (int j = k >> 1; j > 0; j >>= 1) {
            int ixj = tid ^ j;
            if (ixj > tid) {
                bool up = ((tid & k) == 0);
                #pragma unroll
                for (int ql = 0; ql < 4; ql++) {
                    unsigned long long A = keys[ql][tid], B = keys[ql][ixj];
                    if ((A > B) == up) { keys[ql][tid] = B; keys[ql][ixj] = A; }
                }
            }
            __syncthreads();
        }

    // ---- epilogue: warps 0..3, one query each; K=7 relaxations via shfl ----
    int wq = tid >> 5, lane = tid & 31;
    if (wq < 4) {
        int ql = wq;
        int q = qpix[ql];
        float tau = g_tau[q];
        int o1 = (int)(keys[ql][lane]      & 0xffffffffull);
        int o2 = (int)(keys[ql][lane + 32] & 0xffffffffull);
        float l1 = -dv[ql][o1] / tau;
        float l2 = -dv[ql][o2] / tau;
        {
            int r = toprl[ql] + o1 / WSZ, c = leftcl[ql] + o1 % WSZ;
            g_inds[q * KS + lane] = r * HP + c;
            r = toprl[ql] + o2 / WSZ; c = leftcl[ql] + o2 % WSZ;
            g_inds[q * KS + lane + 32] = r * HP + c;
        }
        #pragma unroll
        for (int k = 0; k < KAGG; k++) {
            float m = fmaxf(l1, l2);
            #pragma unroll
            for (int st = 16; st > 0; st >>= 1)
                m = fmaxf(m, __shfl_xor_sync(0xffffffffu, m, st));
            float e1 = expf(l1 - m), e2 = expf(l2 - m);
            float s = e1 + e2;
            #pragma unroll
            for (int st = 16; st > 0; st >>= 1)
                s += __shfl_xor_sync(0xffffffffu, s, st);
            float w1 = e1 / s, w2 = e2 / s;
            g_w[q * 512 + lane * 8 + k] = w1;
            g_w[q * 512 + (lane + 32) * 8 + k] = w2;
            l1 += logf(fmaxf(1.f - w1, 1e-10f));
            l2 += logf(fmaxf(1.f - w2, 1e-10f));
        }
    }
}

// ---------------- kernel 4: zp[q,k,d] = sum_o w[k,o] * px[ind[o], d] ---------
// 128 threads: 2 queries/block, 2 warps per query (o split), f32x2 packed FMA
__global__ void zp_kernel() {
    int tid = threadIdx.x;
    int lane = tid & 31;
    int wid  = tid >> 5;                             // 0..3
    int ql   = wid >> 1;                             // query slot 0/1
    int half = wid & 1;                              // o-half
    int q = blockIdx.x * 2 + ql;

    __shared__ float ws[2][512];
    __shared__ int   is[2][64];
    __shared__ ulonglong2 part[2][KAGG][32];

    int t2 = tid & 63;
    int qslot = tid >> 6;                            // == ql
    int qg = blockIdx.x * 2 + qslot;
    for (int i = t2; i < 512; i += 64) ws[qslot][i] = g_w[qg * 512 + i];
    if (t2 < 64) is[qslot][t2] = g_inds[qg * 64 + t2];
    __syncthreads();

    unsigned long long accA[KAGG], accB[KAGG];
    #pragma unroll
    for (int k = 0; k < KAGG; k++) { accA[k] = 0ull; accB[k] = 0ull; }

    const ulonglong2* px = reinterpret_cast<const ulonglong2*>(g_px4);
    int obase = half * 32;
    for (int oi = 0; oi < 32; oi++) {
        int o = obase + oi;
        int ind = is[ql][o];
        ulonglong2 v = px[ind * 32 + lane];          // float4 as 2 packed f32x2
        const float* wrow = &ws[ql][o * 8];
        #pragma unroll
        for (int k = 0; k < KAGG; k++) {
            float wv = wrow[k];
            unsigned long long wd;
            asm("mov.b64 %0, {%1, %1};" : "=l"(wd) : "f"(wv));
            asm("fma.rn.f32x2 %0, %1, %2, %0;" : "+l"(accA[k]) : "l"(v.x), "l"(wd));
            asm("fma.rn.f32x2 %0, %1, %2, %0;" : "+l"(accB[k]) : "l"(v.y), "l"(wd));
        }
    }

    if (half == 1) {
        #pragma unroll
        for (int k = 0; k < KAGG; k++)
            part[ql][k][lane] = make_ulonglong2(accA[k], accB[k]);
    }
    __syncthreads();
    if (half == 0) {
        ulonglong2* zp = reinterpret_cast<ulonglong2*>(g_zp4);
        #pragma unroll
        for (int k = 0; k < KAGG; k++) {
            ulonglong2 pb = part[ql][k][lane];
            unsigned long long a = accA[k], b = accB[k];
            asm("add.rn.f32x2 %0, %0, %1;" : "+l"(a) : "l"(pb.x));
            asm("add.rn.f32x2 %0, %0, %1;" : "+l"(b) : "l"(pb.y));
            zp[(q * KAGG + k) * 32 + lane] = make_ulonglong2(a, b);
        }
    }
}

// ---------------- kernel 5: fold, smem-tiled --------------------------------
// block = 8x8 output tile, one kk, 4 channels (half). Stage the 11x11 q-row
// region coalesced into smem (121 x 64 floats, row stride 65 vs bank conflict),
// then 1 output per thread from 16 LDS.
__global__ void fold_kernel(const float* __restrict__ y, float* __restrict__ out) {
    __shared__ float s[121 * 65];                    // 31.5KB
    int tile = blockIdx.x;                           // 0..63
    int kk   = blockIdx.y;                           // 0..6
    int chh  = blockIdx.z;                           // 0..1
    int oy0 = (tile >> 3) * 8, ox0 = (tile & 7) * 8;
    int tid = threadIdx.x;                           // 256

    const float* zp = (const float*)g_zp4;
    #pragma unroll
    for (int t = 0; t < 31; t++) {                   // 31*256 = 7936 >= 7744
        int i = t * 256 + tid;
        if (i < 121 * 64) {
            int row = i >> 6, c = i & 63;
            int qi = oy0 + (row / 11), qj = ox0 + (row % 11);
            float v = 0.f;
            if (qi < HP && qj < HP) {
                int q = qi * HP + qj;
                v = zp[q * (KAGG * 128) + kk * 128 + chh * 64 + c];
            }
            s[row * 65 + c] = v;
        }
    }
    __syncthreads();

    int ch_l = tid & 3;                              // channel within half
    int pos = tid >> 2;                              // 0..63
    int ox_l = pos & 7, oy_l = pos >> 3;
    int ti = oy0 + oy_l + 1, tj = ox0 + ox_l + 1;    // padded coords
    float sum = 0.f;
    #pragma unroll
    for (int a = 0; a < 4; a++) {
        #pragma unroll
        for (int b = 0; b < 4; b++) {
            int qi_l = oy_l + 3 - a, qj_l = ox_l + 3 - b;
            sum += s[(qi_l * 11 + qj_l) * 65 + ch_l * 16 + a * 4 + b];
        }
    }
    float cnti = (ti == HO) ? 3.f : 4.f;
    float cntj = (tj == HO) ? 3.f : 4.f;
    float z = sum / (cnti * cntj + 1e-10f);
    int ch = chh * 4 + ch_l;                         // 0..7
    int cho = 8 + kk * 8 + ch;
    int pix = (oy0 + oy_l) * 64 + (ox0 + ox_l);
    out[cho * 4096 + pix] = z - y[ch * 4096 + pix];
}

// ---------------- launch -----------------------------------------------------
extern "C" void kernel_launch(void* const* d_in, const int* in_sizes, int n_in,
                              void* d_out, int out_size) {
    const float* x  = (const float*)d_in[0];
    const float* xe = (const float*)d_in[1];
    const float* ye = (const float*)d_in[2];
    const float* y  = (const float*)d_in[3];
    const float* lt = (const float*)d_in[4];
    float* out = (float*)d_out;

    px_kernel    <<<QQ, 128>>>(x);                   // launch 0
    embed_kernel <<<QQ, 64>>>(xe, ye, lt);           // launch 1
    copy_y_kernel<<<128, 256>>>(y, out);             // launch 2
    dist_kernel  <<<33 * 33, 256>>>();               // launch 3 (ncu capture slot)
    zp_kernel    <<<QQ / 2, 128>>>();                // launch 4
    fold_kernel  <<<dim3(64, KAGG, 2), 256>>>(y, out);// launch 5
}

// round 9
// speedup vs baseline: 1.2126x; 1.2126x over previous
#include <cuda_runtime.h>

// Problem constants (fixed shapes: T=1, C=8, E=4, H=W=64)
#define HP   66            // padded H=W (64+2)
#define QQ   4356          // HP*HP
#define HO   64            // original H=W
#define WSZ  15            // search window side
#define NC   225           // WSZ*WSZ candidates
#define KS   64            // top-k kept
#define KAGG 7             // aggregated volumes
#define BIGD 1e10f

// ---------------- scratch (device globals; no allocation allowed) ------------
__device__ float4 g_pexT4[16 * QQ];       // xe patch embeddings, TRANSPOSED [chunk][q]
__device__ float4 g_pey4 [QQ * 16];       // (Q,64) ye patch embeddings (row-major)
__device__ float4 g_px4  [QQ * 32];       // (Q,128) x patches
__device__ float4 g_zp4  [QQ * KAGG * 32];// (Q,7,128) weighted patch sums
__device__ float  g_w    [QQ * 512];      // (Q,64,8) weights, [o*8+k], k<7 used
__device__ int    g_inds [QQ * KS];       // selected candidate pixel indices
__device__ float  g_qn   [QQ];            // ||pey||^2
__device__ float  g_tau  [QQ];            // exp(avg log_temp patch)

// ---------------- kernel 0: x patches ---------------------------------------
__global__ void px_kernel(const float* __restrict__ x) {
    int q = blockIdx.x, tid = threadIdx.x;          // 128 threads
    int qi = q / HP, qj = q % HP;
    int p = tid & 15, ch = tid >> 4;
    int a = p >> 2, b = p & 3;
    int i = qi + a - 3, j = qj + b - 3;
    bool inb = ((unsigned)i < 64u) && ((unsigned)j < 64u);
    ((float*)g_px4)[q * 128 + tid] = inb ? x[ch * 4096 + i * 64 + j] : 0.f;
}

// ---------------- kernel 1: xe/ye patches + norm + temperature ---------------
__global__ void embed_kernel(const float* __restrict__ xe,
                             const float* __restrict__ ye,
                             const float* __restrict__ ltin) {
    int q = blockIdx.x, tid = threadIdx.x;          // 64 threads
    int qi = q / HP, qj = q % HP;
    int p = tid & 15, ch = tid >> 4;                // ch 0..3, d = ch*16+p = tid
    int a = p >> 2, b = p & 3;
    int i = qi + a - 3, j = qj + b - 3;             // original-image coords
    bool inb = ((unsigned)i < 64u) && ((unsigned)j < 64u);

    float vx = inb ? xe[ch * 4096 + i * 64 + j] : 0.f;
    float vy = inb ? ye[ch * 4096 + i * 64 + j] : 0.f;
    // transposed xe storage: float index chunk*(QQ*4) + q*4 + comp
    ((float*)g_pexT4)[(tid >> 2) * (QQ * 4) + q * 4 + (tid & 3)] = vx;
    ((float*)g_pey4)[q * 64 + tid] = vy;

    __shared__ float sm[64];
    sm[tid] = vy * vy;
    __syncthreads();
    for (int st = 32; st > 0; st >>= 1) { if (tid < st) sm[tid] += sm[tid + st]; __syncthreads(); }
    if (tid == 0) g_qn[q] = sm[0];
    __syncthreads();

    float lv = 0.f;
    if (tid < 16 && inb) lv = ltin[i * 64 + j];      // tid<16 -> ch==0, p==tid
    sm[tid] = (tid < 16) ? lv : 0.f;
    __syncthreads();
    for (int st = 32; st > 0; st >>= 1) { if (tid < st) sm[tid] += sm[tid + st]; __syncthreads(); }
    if (tid == 0) g_tau[q] = expf(sm[0] * (1.f / 16.f));
}

// ---------------- kernel 2: passthrough of y into first 8 output channels ---
__global__ void copy_y_kernel(const float* __restrict__ y, float* __restrict__ out) {
    int idx = blockIdx.x * blockDim.x + threadIdx.x; // 32768 threads
    out[idx] = y[idx];
}

// inverse of the monotone sortable-float transform
__device__ __forceinline__ float inv_sortable(unsigned s) {
    unsigned b = (s & 0x80000000u) ? (s & 0x7fffffffu) : ~s;
    return __uint_as_float(b);
}

// ---------------- kernel 3: tiled distances + register top-64 + NNN weights -
// One block = 2x2 query tile. Shared 16x16 candidate-window union staged in
// smem (two passes of 8 float4-chunks). Top-64 selection: one warp per query,
// full 256-key bitonic sort IN REGISTERS (8 u64 keys/lane, shfl for cross-lane
// stages) -- zero LDS, zero barriers in the sort.
__global__ void dist_kernel() {
    int tid = threadIdx.x;                           // 256 threads
    int bi = blockIdx.x;                             // 33*33 tiles
    int tile_i = (bi / 33) * 2, tile_j = (bi % 33) * 2;

    __shared__ float4 wsm[8][256];                   // 32KB window chunk-slab
    __shared__ unsigned long long keys[4][256];      // 8KB sort keys
    __shared__ float  cns[256];                      // candidate norms
    __shared__ float4 peys[4][16];                   // query embeddings

    int topr0  = min(max(tile_i - 7, 0), HP - WSZ);
    int leftc0 = min(max(tile_j - 7, 0), HP - WSZ);

    // per-query window anchors (offset 0/1 from union base)
    int toprl[4], leftcl[4], qpix[4];
    #pragma unroll
    for (int ql = 0; ql < 4; ql++) {
        int qi = tile_i + (ql >> 1), qj = tile_j + (ql & 1);
        toprl[ql]  = min(max(qi - 7, 0), HP - WSZ);
        leftcl[ql] = min(max(qj - 7, 0), HP - WSZ);
        qpix[ql]   = qi * HP + qj;
    }

    if (tid < 64) peys[tid >> 4][tid & 15] = g_pey4[qpix[tid >> 4] * 16 + (tid & 15)];

    // candidate pixel for this thread (clamped; clamped slots never referenced)
    int crow = min(topr0 + (tid >> 4), HP - 1);
    int ccol = min(leftc0 + (tid & 15), HP - 1);
    int cpix = crow * HP + ccol;

    float cnacc = 0.f;
    float crossA[4];

    // ---- pass 0: chunks 0..7 ----
    #pragma unroll
    for (int i = 0; i < 8; i++) {
        float4 v = g_pexT4[i * QQ + cpix];
        wsm[i][tid] = v;
        cnacc += v.x * v.x + v.y * v.y + v.z * v.z + v.w * v.w;
    }
    __syncthreads();
    {
        int wr = tid / WSZ, wc = tid - wr * WSZ;     // window-local coords
        #pragma unroll
        for (int ql = 0; ql < 4; ql++) {
            float acc = 0.f;
            if (tid < NC) {
                int cidx = (wr + toprl[ql] - topr0) * 16 + (wc + leftcl[ql] - leftc0);
                #pragma unroll
                for (int i = 0; i < 8; i++) {
                    float4 v = wsm[i][cidx]; float4 u = peys[ql][i];
                    acc += v.x * u.x + v.y * u.y + v.z * u.z + v.w * u.w;
                }
            }
            crossA[ql] = acc;
        }
    }
    __syncthreads();

    // ---- pass 1: chunks 8..15, build sort keys directly ----
    #pragma unroll
    for (int i = 0; i < 8; i++) {
        float4 v = g_pexT4[(8 + i) * QQ + cpix];
        wsm[i][tid] = v;
        cnacc += v.x * v.x + v.y * v.y + v.z * v.z + v.w * v.w;
    }
    cns[tid] = cnacc;
    __syncthreads();
    {
        int wr = tid / WSZ, wc = tid - wr * WSZ;
        #pragma unroll
        for (int ql = 0; ql < 4; ql++) {
            unsigned long long key = 0xFFFFFFFFFFFFFFFFull;
            if (tid < NC) {
                int cidx = (wr + toprl[ql] - topr0) * 16 + (wc + leftcl[ql] - leftc0);
                float acc = crossA[ql];
                #pragma unroll
                for (int i = 0; i < 8; i++) {
                    float4 v = wsm[i][cidx]; float4 u = peys[ql][8 + i];
                    acc += v.x * u.x + v.y * u.y + v.z * u.z + v.w * u.w;
                }
                int pr = toprl[ql] + wr, pc = leftcl[ql] + wc;
                int pix = pr * HP + pc;
                float d = g_qn[qpix[ql]] + cns[cidx] - 2.f * acc;
                if (pix == qpix[ql]) d = BIGD;       // remove_self
                unsigned u = __float_as_uint(d);
                u = (u & 0x80000000u) ? ~u : (u | 0x80000000u);
                key = ((unsigned long long)u << 32) | (unsigned)tid;
            }
            keys[ql][tid] = key;
        }
    }
    __syncthreads();

    // ---- warps 0..3: register bitonic sort of 256 keys, one query each ----
    int wq = tid >> 5, lane = tid & 31;
    if (wq < 4) {
        unsigned long long K[8];                     // element e = lane*8 + r
        #pragma unroll
        for (int r = 0; r < 8; r++) K[r] = keys[wq][lane * 8 + r];

        #pragma unroll
        for (int k = 2; k <= 256; k <<= 1) {
            #pragma unroll
            for (int j = k >> 1; j > 0; j >>= 1) {
                if (j >= 8) {
                    int m = j >> 3;                  // lane xor distance
                    bool lowlane = ((lane & m) == 0);
                    #pragma unroll
                    for (int r = 0; r < 8; r++) {
                        unsigned long long other = __shfl_xor_sync(0xffffffffu, K[r], m);
                        bool asc = (((lane * 8 + r) & k) == 0);
                        bool keepmin = (asc == lowlane);
                        bool lt = (K[r] < other);
                        K[r] = (keepmin == lt) ? K[r] : other;
                    }
                } else {
                    #pragma unroll
                    for (int r = 0; r < 8; r++) {
                        int rp = r ^ j;
                        if (rp > r) {
                            bool asc = (((lane * 8 + r) & k) == 0);
                            unsigned long long a = K[r], b = K[rp];
                            bool sw = asc ? (a > b) : (a < b);
                            if (sw) { K[r] = b; K[rp] = a; }
                        }
                    }
                }
            }
        }

        // winners (ranks 0..63) live in lanes 0..7; park them in smem region
        // keys[wq][0..63] (warp-private now) for the epilogue redistribution
        if (lane < 8) {
            #pragma unroll
            for (int r = 0; r < 8; r++) keys[wq][lane * 8 + r] = K[r];
        }
        __syncwarp();

        // ---- epilogue: K=7 continuous relaxations via shfl (2 logits/lane) --
        int q = qpix[wq];
        float tau = g_tau[q];
        unsigned long long k1 = keys[wq][lane];
        unsigned long long k2 = keys[wq][lane + 32];
        int o1 = (int)(k1 & 0xffffffffull);
        int o2 = (int)(k2 & 0xffffffffull);
        float l1 = -inv_sortable((unsigned)(k1 >> 32)) / tau;
        float l2 = -inv_sortable((unsigned)(k2 >> 32)) / tau;
        {
            int r = toprl[wq] + o1 / WSZ, c = leftcl[wq] + o1 % WSZ;
            g_inds[q * KS + lane] = r * HP + c;
            r = toprl[wq] + o2 / WSZ; c = leftcl[wq] + o2 % WSZ;
            g_inds[q * KS + lane + 32] = r * HP + c;
        }
        #pragma unroll
        for (int k = 0; k < KAGG; k++) {
            float m = fmaxf(l1, l2);
            #pragma unroll
            for (int st = 16; st > 0; st >>= 1)
                m = fmaxf(m, __shfl_xor_sync(0xffffffffu, m, st));
            float e1 = expf(l1 - m), e2 = expf(l2 - m);
            float s = e1 + e2;
            #pragma unroll
            for (int st = 16; st > 0; st >>= 1)
                s += __shfl_xor_sync(0xffffffffu, s, st);
            float w1 = e1 / s, w2 = e2 / s;
            g_w[q * 512 + lane * 8 + k] = w1;
            g_w[q * 512 + (lane + 32) * 8 + k] = w2;
            l1 += logf(fmaxf(1.f - w1, 1e-10f));
            l2 += logf(fmaxf(1.f - w2, 1e-10f));
        }
    }
}

// ---------------- kernel 4: zp[q,k,d] = sum_o w[k,o] * px[ind[o], d] ---------
// 128 threads: 2 queries/block, 2 warps per query (o split), f32x2 packed FMA
__global__ void zp_kernel() {
    int tid = threadIdx.x;
    int lane = tid & 31;
    int wid  = tid >> 5;                             // 0..3
    int ql   = wid >> 1;                             // query slot 0/1
    int half = wid & 1;                              // o-half
    int q = blockIdx.x * 2 + ql;

    __shared__ float ws[2][512];
    __shared__ int   is[2][64];
    __shared__ ulonglong2 part[2][KAGG][32];

    int t2 = tid & 63;
    int qslot = tid >> 6;                            // == ql
    int qg = blockIdx.x * 2 + qslot;
    for (int i = t2; i < 512; i += 64) ws[qslot][i] = g_w[qg * 512 + i];
    if (t2 < 64) is[qslot][t2] = g_inds[qg * 64 + t2];
    __syncthreads();

    unsigned long long accA[KAGG], accB[KAGG];
    #pragma unroll
    for (int k = 0; k < KAGG; k++) { accA[k] = 0ull; accB[k] = 0ull; }

    const ulonglong2* px = reinterpret_cast<const ulonglong2*>(g_px4);
    int obase = half * 32;
    for (int oi = 0; oi < 32; oi++) {
        int o = obase + oi;
        int ind = is[ql][o];
        ulonglong2 v = px[ind * 32 + lane];          // float4 as 2 packed f32x2
        const float* wrow = &ws[ql][o * 8];
        #pragma unroll
        for (int k = 0; k < KAGG; k++) {
            float wv = wrow[k];
            unsigned long long wd;
            asm("mov.b64 %0, {%1, %1};" : "=l"(wd) : "f"(wv));
            asm("fma.rn.f32x2 %0, %1, %2, %0;" : "+l"(accA[k]) : "l"(v.x), "l"(wd));
            asm("fma.rn.f32x2 %0, %1, %2, %0;" : "+l"(accB[k]) : "l"(v.y), "l"(wd));
        }
    }

    if (half == 1) {
        #pragma unroll
        for (int k = 0; k < KAGG; k++)
            part[ql][k][lane] = make_ulonglong2(accA[k], accB[k]);
    }
    __syncthreads();
    if (half == 0) {
        ulonglong2* zp = reinterpret_cast<ulonglong2*>(g_zp4);
        #pragma unroll
        for (int k = 0; k < KAGG; k++) {
            ulonglong2 pb = part[ql][k][lane];
            unsigned long long a = accA[k], b = accB[k];
            asm("add.rn.f32x2 %0, %0, %1;" : "+l"(a) : "l"(pb.x));
            asm("add.rn.f32x2 %0, %0, %1;" : "+l"(b) : "l"(pb.y));
            zp[(q * KAGG + k) * 32 + lane] = make_ulonglong2(a, b);
        }
    }
}

// ---------------- kernel 5: fold, smem-tiled --------------------------------
// block = 8x8 output tile, one kk, 4 channels (half). Stage the 11x11 q-row
// region coalesced into smem (121 x 64 floats, row stride 65 vs bank conflict),
// then 1 output per thread from 16 LDS.
__global__ void fold_kernel(const float* __restrict__ y, float* __restrict__ out) {
    __shared__ float s[121 * 65];                    // 31.5KB
    int tile = blockIdx.x;                           // 0..63
    int kk   = blockIdx.y;                           // 0..6
    int chh  = blockIdx.z;                           // 0..1
    int oy0 = (tile >> 3) * 8, ox0 = (tile & 7) * 8;
    int tid = threadIdx.x;                           // 256

    const float* zp = (const float*)g_zp4;
    #pragma unroll
    for (int t = 0; t < 31; t++) {                   // 31*256 = 7936 >= 7744
        int i = t * 256 + tid;
        if (i < 121 * 64) {
            int row = i >> 6, c = i & 63;
            int qi = oy0 + (row / 11), qj = ox0 + (row % 11);
            float v = 0.f;
            if (qi < HP && qj < HP) {
                int q = qi * HP + qj;
                v = zp[q * (KAGG * 128) + kk * 128 + chh * 64 + c];
            }
            s[row * 65 + c] = v;
        }
    }
    __syncthreads();

    int ch_l = tid & 3;                              // channel within half
    int pos = tid >> 2;                              // 0..63
    int ox_l = pos & 7, oy_l = pos >> 3;
    int ti = oy0 + oy_l + 1, tj = ox0 + ox_l + 1;    // padded coords
    float sum = 0.f;
    #pragma unroll
    for (int a = 0; a < 4; a++) {
        #pragma unroll
        for (int b = 0; b < 4; b++) {
            int qi_l = oy_l + 3 - a, qj_l = ox_l + 3 - b;
            sum += s[(qi_l * 11 + qj_l) * 65 + ch_l * 16 + a * 4 + b];
        }
    }
    float cnti = (ti == HO) ? 3.f : 4.f;
    float cntj = (tj == HO) ? 3.f : 4.f;
    float z = sum / (cnti * cntj + 1e-10f);
    int ch = chh * 4 + ch_l;                         // 0..7
    int cho = 8 + kk * 8 + ch;
    int pix = (oy0 + oy_l) * 64 + (ox0 + ox_l);
    out[cho * 4096 + pix] = z - y[ch * 4096 + pix];
}

// ---------------- launch -----------------------------------------------------
extern "C" void kernel_launch(void* const* d_in, const int* in_sizes, int n_in,
                              void* d_out, int out_size) {
    const float* x  = (const float*)d_in[0];
    const float* xe = (const float*)d_in[1];
    const float* ye = (const float*)d_in[2];
    const float* y  = (const float*)d_in[3];
    const float* lt = (const float*)d_in[4];
    float* out = (float*)d_out;

    px_kernel    <<<QQ, 128>>>(x);                   // launch 0
    embed_kernel <<<QQ, 64>>>(xe, ye, lt);           // launch 1
    copy_y_kernel<<<128, 256>>>(y, out);             // launch 2
    dist_kernel  <<<33 * 33, 256>>>();               // launch 3 (ncu capture slot)
    zp_kernel    <<<QQ / 2, 128>>>();                // launch 4
    fold_kernel  <<<dim3(64, KAGG, 2), 256>>>(y, out);// launch 5
}

// round 13
// speedup vs baseline: 1.4966x; 1.2341x over previous
#include <cuda_runtime.h>

// Problem constants (fixed shapes: T=1, C=8, E=4, H=W=64)
#define HP   66            // padded H=W (64+2)
#define QQ   4356          // HP*HP
#define HO   64            // original H=W
#define WSZ  15            // search window side
#define NC   225           // WSZ*WSZ candidates
#define KS   64            // top-k kept
#define KAGG 7             // aggregated volumes
#define BIGD 1e10f

// ---------------- scratch (device globals; no allocation allowed) ------------
__device__ float4 g_pexT4[16 * QQ];       // xe patch embeddings, TRANSPOSED [chunk][q]
__device__ float4 g_pey4 [QQ * 16];       // (Q,64) ye patch embeddings (row-major)
__device__ float4 g_px4  [QQ * 32];       // (Q,128) x patches
__device__ float4 g_zp4  [QQ * KAGG * 32];// (Q,7,128) weighted patch sums
__device__ float  g_w    [QQ * 512];      // (Q,64,8) weights, [o*8+k], k<7 used
__device__ int    g_inds [QQ * KS];       // selected candidate pixel indices
__device__ float  g_qn   [QQ];            // ||pey||^2
__device__ float  g_tau  [QQ];            // exp(avg log_temp patch)

// ---------------- kernel 0: x patches ---------------------------------------
__global__ void px_kernel(const float* __restrict__ x) {
    int q = blockIdx.x, tid = threadIdx.x;          // 128 threads
    int qi = q / HP, qj = q % HP;
    int p = tid & 15, ch = tid >> 4;
    int a = p >> 2, b = p & 3;
    int i = qi + a - 3, j = qj + b - 3;
    bool inb = ((unsigned)i < 64u) && ((unsigned)j < 64u);
    ((float*)g_px4)[q * 128 + tid] = inb ? x[ch * 4096 + i * 64 + j] : 0.f;
}

// ---------------- kernel 1: xe/ye patches + norm + temperature ---------------
__global__ void embed_kernel(const float* __restrict__ xe,
                             const float* __restrict__ ye,
                             const float* __restrict__ ltin) {
    int q = blockIdx.x, tid = threadIdx.x;          // 64 threads
    int qi = q / HP, qj = q % HP;
    int p = tid & 15, ch = tid >> 4;                // ch 0..3, d = ch*16+p = tid
    int a = p >> 2, b = p & 3;
    int i = qi + a - 3, j = qj + b - 3;             // original-image coords
    bool inb = ((unsigned)i < 64u) && ((unsigned)j < 64u);

    float vx = inb ? xe[ch * 4096 + i * 64 + j] : 0.f;
    float vy = inb ? ye[ch * 4096 + i * 64 + j] : 0.f;
    // transposed xe storage: float index chunk*(QQ*4) + q*4 + comp
    ((float*)g_pexT4)[(tid >> 2) * (QQ * 4) + q * 4 + (tid & 3)] = vx;
    ((float*)g_pey4)[q * 64 + tid] = vy;

    __shared__ float sm[64];
    sm[tid] = vy * vy;
    __syncthreads();
    for (int st = 32; st > 0; st >>= 1) { if (tid < st) sm[tid] += sm[tid + st]; __syncthreads(); }
    if (tid == 0) g_qn[q] = sm[0];
    __syncthreads();

    float lv = 0.f;
    if (tid < 16 && inb) lv = ltin[i * 64 + j];      // tid<16 -> ch==0, p==tid
    sm[tid] = (tid < 16) ? lv : 0.f;
    __syncthreads();
    for (int st = 32; st > 0; st >>= 1) { if (tid < st) sm[tid] += sm[tid + st]; __syncthreads(); }
    if (tid == 0) g_tau[q] = expf(sm[0] * (1.f / 16.f));
}

// ---------------- kernel 2: passthrough of y into first 8 output channels ---
__global__ void copy_y_kernel(const float* __restrict__ y, float* __restrict__ out) {
    int idx = blockIdx.x * blockDim.x + threadIdx.x; // 32768 threads
    out[idx] = y[idx];
}

// inverse of the monotone sortable-float transform
__device__ __forceinline__ float inv_sortable(unsigned s) {
    unsigned b = (s & 0x80000000u) ? (s & 0x7fffffffu) : ~s;
    return __uint_as_float(b);
}

// ---------------- kernel 3: candidate-centric distances + register top-64 ---
// One block = 2x2 query tile over a 16x16 candidate union. Each thread OWNS one
// union pixel: it loads that pixel's 16 embedding chunks from global (coalesced)
// and computes its distance to all 4 queries from registers (pey via broadcast
// LDS). Keys scattered to per-query window slots; no staging smem at all.
// Top-64: one warp per query, full 256-key bitonic sort in registers.
__global__ void dist_kernel() {
    int tid = threadIdx.x;                           // 256 threads
    int bi = blockIdx.x;                             // 33*33 tiles
    int tile_i = (bi / 33) * 2, tile_j = (bi % 33) * 2;

    __shared__ unsigned long long keys[4][256];      // 8KB sort keys
    __shared__ float4 peys[4][16];                   // query embeddings

    int topr0  = min(max(tile_i - 7, 0), HP - WSZ);
    int leftc0 = min(max(tile_j - 7, 0), HP - WSZ);

    // per-query window anchors (offset 0/1 from union base)
    int toprl[4], leftcl[4], qpix[4];
    #pragma unroll
    for (int ql = 0; ql < 4; ql++) {
        int qi = tile_i + (ql >> 1), qj = tile_j + (ql & 1);
        toprl[ql]  = min(max(qi - 7, 0), HP - WSZ);
        leftcl[ql] = min(max(qj - 7, 0), HP - WSZ);
        qpix[ql]   = qi * HP + qj;
    }

    if (tid < 64) peys[tid >> 4][tid & 15] = g_pey4[qpix[tid >> 4] * 16 + (tid & 15)];
    #pragma unroll
    for (int ql = 0; ql < 4; ql++) keys[ql][tid] = 0xFFFFFFFFFFFFFFFFull;
    __syncthreads();

    // candidate pixel owned by this thread (clamp duplicates are benign: they
    // recompute identical keys for identical pixels)
    int crow = min(topr0 + (tid >> 4), HP - 1);
    int ccol = min(leftc0 + (tid & 15), HP - 1);
    int cpix = crow * HP + ccol;

    float cn = 0.f, cr0 = 0.f, cr1 = 0.f, cr2 = 0.f, cr3 = 0.f;
    #pragma unroll
    for (int i = 0; i < 16; i++) {
        float4 v = g_pexT4[i * QQ + cpix];
        cn += v.x * v.x + v.y * v.y + v.z * v.z + v.w * v.w;
        float4 u0 = peys[0][i];
        cr0 += v.x * u0.x + v.y * u0.y + v.z * u0.z + v.w * u0.w;
        float4 u1 = peys[1][i];
        cr1 += v.x * u1.x + v.y * u1.y + v.z * u1.z + v.w * u1.w;
        float4 u2 = peys[2][i];
        cr2 += v.x * u2.x + v.y * u2.y + v.z * u2.z + v.w * u2.w;
        float4 u3 = peys[3][i];
        cr3 += v.x * u3.x + v.y * u3.y + v.z * u3.z + v.w * u3.w;
    }

    float crs[4] = {cr0, cr1, cr2, cr3};
    #pragma unroll
    for (int ql = 0; ql < 4; ql++) {
        int wr = crow - toprl[ql], wc = ccol - leftcl[ql];
        if (((unsigned)wr < (unsigned)WSZ) && ((unsigned)wc < (unsigned)WSZ)) {
            float d = g_qn[qpix[ql]] + cn - 2.f * crs[ql];
            if (cpix == qpix[ql]) d = BIGD;          // remove_self
            unsigned u = __float_as_uint(d);
            u = (u & 0x80000000u) ? ~u : (u | 0x80000000u);
            int o = wr * WSZ + wc;                   // candidate slot in window
            keys[ql][o] = ((unsigned long long)u << 32) | (unsigned)o;
        }
    }
    __syncthreads();

    // ---- warps 0..3: register bitonic sort of 256 keys, one query each ----
    int wq = tid >> 5, lane = tid & 31;
    if (wq < 4) {
        unsigned long long K[8];                     // element e = lane*8 + r
        #pragma unroll
        for (int r = 0; r < 8; r++) K[r] = keys[wq][lane * 8 + r];

        #pragma unroll
        for (int k = 2; k <= 256; k <<= 1) {
            #pragma unroll
            for (int j = k >> 1; j > 0; j >>= 1) {
                if (j >= 8) {
                    int m = j >> 3;                  // lane xor distance
                    bool lowlane = ((lane & m) == 0);
                    #pragma unroll
                    for (int r = 0; r < 8; r++) {
                        unsigned long long other = __shfl_xor_sync(0xffffffffu, K[r], m);
                        bool asc = (((lane * 8 + r) & k) == 0);
                        bool keepmin = (asc == lowlane);
                        bool lt = (K[r] < other);
                        K[r] = (keepmin == lt) ? K[r] : other;
                    }
                } else {
                    #pragma unroll
                    for (int r = 0; r < 8; r++) {
                        int rp = r ^ j;
                        if (rp > r) {
                            bool asc = (((lane * 8 + r) & k) == 0);
                            unsigned long long a = K[r], b = K[rp];
                            bool sw = asc ? (a > b) : (a < b);
                            if (sw) { K[r] = b; K[rp] = a; }
                        }
                    }
                }
            }
        }

        // winners (ranks 0..63) live in lanes 0..7; park them in smem region
        // keys[wq][0..63] (warp-private now) for the epilogue redistribution
        if (lane < 8) {
            #pragma unroll
            for (int r = 0; r < 8; r++) keys[wq][lane * 8 + r] = K[r];
        }
        __syncwarp();

        // ---- epilogue: K=7 continuous relaxations via shfl (2 logits/lane) --
        int q = qpix[wq];
        float tau = g_tau[q];
        unsigned long long k1 = keys[wq][lane];
        unsigned long long k2 = keys[wq][lane + 32];
        int o1 = (int)(k1 & 0xffffffffull);
        int o2 = (int)(k2 & 0xffffffffull);
        float l1 = -inv_sortable((unsigned)(k1 >> 32)) / tau;
        float l2 = -inv_sortable((unsigned)(k2 >> 32)) / tau;
        {
            int r = toprl[wq] + o1 / WSZ, c = leftcl[wq] + o1 % WSZ;
            g_inds[q * KS + lane] = r * HP + c;
            r = toprl[wq] + o2 / WSZ; c = leftcl[wq] + o2 % WSZ;
            g_inds[q * KS + lane + 32] = r * HP + c;
        }
        #pragma unroll
        for (int k = 0; k < KAGG; k++) {
            float m = fmaxf(l1, l2);
            #pragma unroll
            for (int st = 16; st > 0; st >>= 1)
                m = fmaxf(m, __shfl_xor_sync(0xffffffffu, m, st));
            float e1 = expf(l1 - m), e2 = expf(l2 - m);
            float s = e1 + e2;
            #pragma unroll
            for (int st = 16; st > 0; st >>= 1)
                s += __shfl_xor_sync(0xffffffffu, s, st);
            float w1 = e1 / s, w2 = e2 / s;
            g_w[q * 512 + lane * 8 + k] = w1;
            g_w[q * 512 + (lane + 32) * 8 + k] = w2;
            l1 += logf(fmaxf(1.f - w1, 1e-10f));
            l2 += logf(fmaxf(1.f - w2, 1e-10f));
        }
    }
}

// ---------------- kernel 4: zp[q,k,d] = sum_o w[k,o] * px[ind[o], d] ---------
// 128 threads: 2 queries/block, 2 warps per query (o split), f32x2 packed FMA
__global__ void zp_kernel() {
    int tid = threadIdx.x;
    int lane = tid & 31;
    int wid  = tid >> 5;                             // 0..3
    int ql   = wid >> 1;                             // query slot 0/1
    int half = wid & 1;                              // o-half
    int q = blockIdx.x * 2 + ql;

    __shared__ float ws[2][512];
    __shared__ int   is[2][64];
    __shared__ ulonglong2 part[2][KAGG][32];

    int t2 = tid & 63;
    int qslot = tid >> 6;                            // == ql
    int qg = blockIdx.x * 2 + qslot;
    for (int i = t2; i < 512; i += 64) ws[qslot][i] = g_w[qg * 512 + i];
    if (t2 < 64) is[qslot][t2] = g_inds[qg * 64 + t2];
    __syncthreads();

    unsigned long long accA[KAGG], accB[KAGG];
    #pragma unroll
    for (int k = 0; k < KAGG; k++) { accA[k] = 0ull; accB[k] = 0ull; }

    const ulonglong2* px = reinterpret_cast<const ulonglong2*>(g_px4);
    int obase = half * 32;
    for (int oi = 0; oi < 32; oi++) {
        int o = obase + oi;
        int ind = is[ql][o];
        ulonglong2 v = px[ind * 32 + lane];          // float4 as 2 packed f32x2
        const float* wrow = &ws[ql][o * 8];
        #pragma unroll
        for (int k = 0; k < KAGG; k++) {
            float wv = wrow[k];
            unsigned long long wd;
            asm("mov.b64 %0, {%1, %1};" : "=l"(wd) : "f"(wv));
            asm("fma.rn.f32x2 %0, %1, %2, %0;" : "+l"(accA[k]) : "l"(v.x), "l"(wd));
            asm("fma.rn.f32x2 %0, %1, %2, %0;" : "+l"(accB[k]) : "l"(v.y), "l"(wd));
        }
    }

    if (half == 1) {
        #pragma unroll
        for (int k = 0; k < KAGG; k++)
            part[ql][k][lane] = make_ulonglong2(accA[k], accB[k]);
    }
    __syncthreads();
    if (half == 0) {
        ulonglong2* zp = reinterpret_cast<ulonglong2*>(g_zp4);
        #pragma unroll
        for (int k = 0; k < KAGG; k++) {
            ulonglong2 pb = part[ql][k][lane];
            unsigned long long a = accA[k], b = accB[k];
            asm("add.rn.f32x2 %0, %0, %1;" : "+l"(a) : "l"(pb.x));
            asm("add.rn.f32x2 %0, %0, %1;" : "+l"(b) : "l"(pb.y));
            zp[(q * KAGG + k) * 32 + lane] = make_ulonglong2(a, b);
        }
    }
}

// ---------------- kernel 5: fold, smem-tiled --------------------------------
// block = 8x8 output tile, one kk, 4 channels (half). Stage the 11x11 q-row
// region coalesced into smem (121 x 64 floats, row stride 65 vs bank conflict),
// then 1 output per thread from 16 LDS.
__global__ void fold_kernel(const float* __restrict__ y, float* __restrict__ out) {
    __shared__ float s[121 * 65];                    // 31.5KB
    int tile = blockIdx.x;                           // 0..63
    int kk   = blockIdx.y;                           // 0..6
    int chh  = blockIdx.z;                           // 0..1
    int oy0 = (tile >> 3) * 8, ox0 = (tile & 7) * 8;
    int tid = threadIdx.x;                           // 256

    const float* zp = (const float*)g_zp4;
    #pragma unroll
    for (int t = 0; t < 31; t++) {                   // 31*256 = 7936 >= 7744
        int i = t * 256 + tid;
        if (i < 121 * 64) {
            int row = i >> 6, c = i & 63;
            int qi = oy0 + (row / 11), qj = ox0 + (row % 11);
            float v = 0.f;
            if (qi < HP && qj < HP) {
                int q = qi * HP + qj;
                v = zp[q * (KAGG * 128) + kk * 128 + chh * 64 + c];
            }
            s[row * 65 + c] = v;
        }
    }
    __syncthreads();

    int ch_l = tid & 3;                              // channel within half
    int pos = tid >> 2;                              // 0..63
    int ox_l = pos & 7, oy_l = pos >> 3;
    int ti = oy0 + oy_l + 1, tj = ox0 + ox_l + 1;    // padded coords
    float sum = 0.f;
    #pragma unroll
    for (int a = 0; a < 4; a++) {
        #pragma unroll
        for (int b = 0; b < 4; b++) {
            int qi_l = oy_l + 3 - a, qj_l = ox_l + 3 - b;
            sum += s[(qi_l * 11 + qj_l) * 65 + ch_l * 16 + a * 4 + b];
        }
    }
    float cnti = (ti == HO) ? 3.f : 4.f;
    float cntj = (tj == HO) ? 3.f : 4.f;
    float z = sum / (cnti * cntj + 1e-10f);
    int ch = chh * 4 + ch_l;                         // 0..7
    int cho = 8 + kk * 8 + ch;
    int pix = (oy0 + oy_l) * 64 + (ox0 + ox_l);
    out[cho * 4096 + pix] = z - y[ch * 4096 + pix];
}

// ---------------- launch -----------------------------------------------------
extern "C" void kernel_launch(void* const* d_in, const int* in_sizes, int n_in,
                              void* d_out, int out_size) {
    const float* x  = (const float*)d_in[0];
    const float* xe = (const float*)d_in[1];
    const float* ye = (const float*)d_in[2];
    const float* y  = (const float*)d_in[3];
    const float* lt = (const float*)d_in[4];
    float* out = (float*)d_out;

    px_kernel    <<<QQ, 128>>>(x);                   // launch 0
    embed_kernel <<<QQ, 64>>>(xe, ye, lt);           // launch 1
    copy_y_kernel<<<128, 256>>>(y, out);             // launch 2
    dist_kernel  <<<33 * 33, 256>>>();               // launch 3 (ncu capture slot)
    zp_kernel    <<<QQ / 2, 128>>>();                // launch 4
    fold_kernel  <<<dim3(64, KAGG, 2), 256>>>(y, out);// launch 5
}